// round 15
// baseline (speedup 1.0000x reference)
#include <cuda_runtime.h>
#include <cuda_fp16.h>
#include <cstdint>

// Problem constants
#define S_TOK   2048
#define HDIM    2048
#define NHEADS  16
#define HEADDIM 128
#define BATCH   2
#define MROWS   (BATCH * S_TOK)   // 4096

// ---------------------------------------------------------------------------
// Scratch (alloc-free rule: __device__ globals), all single fp16
// ---------------------------------------------------------------------------
__device__ __half g_x16[(size_t)MROWS * HDIM];
__device__ __half g_wtq[(size_t)HDIM * HDIM];
__device__ __half g_wtk[(size_t)HDIM * HDIM];
__device__ __half g_wtv[(size_t)HDIM * HDIM];
__device__ __half g_wto[(size_t)HDIM * HDIM];
__device__ __half g_q16[(size_t)MROWS * HDIM];
__device__ __half g_k16[(size_t)MROWS * HDIM];
__device__ __half g_v16[(size_t)MROWS * HDIM];
__device__ __half g_o16[(size_t)MROWS * HDIM];

// ---------------------------------------------------------------------------
// MMA / ldmatrix / cp.async helpers (portable sm_80+ path; sm_103-safe)
// ---------------------------------------------------------------------------
__device__ __forceinline__ uint32_t smem_to_u32(const void* smem_ptr) {
    uint32_t addr;
    asm("{ .reg .u64 tmp; cvta.to.shared.u64 tmp, %1; cvt.u32.u64 %0, tmp; }"
        : "=r"(addr) : "l"(smem_ptr));
    return addr;
}

__device__ __forceinline__ void ldsm_x4(uint32_t* r, uint32_t addr) {
    asm volatile("ldmatrix.sync.aligned.m8n8.x4.shared.b16 {%0,%1,%2,%3}, [%4];"
                 : "=r"(r[0]), "=r"(r[1]), "=r"(r[2]), "=r"(r[3]) : "r"(addr));
}

__device__ __forceinline__ void ldsm_x4_t(uint32_t* r, uint32_t addr) {
    asm volatile("ldmatrix.sync.aligned.m8n8.x4.trans.shared.b16 {%0,%1,%2,%3}, [%4];"
                 : "=r"(r[0]), "=r"(r[1]), "=r"(r[2]), "=r"(r[3]) : "r"(addr));
}

__device__ __forceinline__ void mma_f16(float* c, const uint32_t* a,
                                        const uint32_t* b) {
    asm volatile(
        "mma.sync.aligned.m16n8k16.row.col.f32.f16.f16.f32 "
        "{%0,%1,%2,%3}, {%4,%5,%6,%7}, {%8,%9}, {%0,%1,%2,%3};"
        : "+f"(c[0]), "+f"(c[1]), "+f"(c[2]), "+f"(c[3])
        : "r"(a[0]), "r"(a[1]), "r"(a[2]), "r"(a[3]), "r"(b[0]), "r"(b[1]));
}

#define CP_ASYNC16(dst, src) \
    asm volatile("cp.async.cg.shared.global [%0], [%1], 16;" \
                 :: "r"((uint32_t)(dst)), "l"(src) : "memory")
#define CP_COMMIT() asm volatile("cp.async.commit_group;" ::: "memory")
#define CP_WAIT1()  asm volatile("cp.async.wait_group 1;" ::: "memory")
#define CP_WAIT0()  asm volatile("cp.async.wait_group 0;" ::: "memory")

__device__ __forceinline__ uint32_t pack_h2(float a, float b) {
    __half2 h = __floats2half2_rn(a, b);
    return *(uint32_t*)&h;
}

// ---------------------------------------------------------------------------
// Fused convert: z<4 -> transpose-convert weight z; z==4 -> elementwise
// convert hidden fp32 -> fp16.
// ---------------------------------------------------------------------------
__global__ __launch_bounds__(256) void convT4_kernel(
    const float* __restrict__ W0, const float* __restrict__ W1,
    const float* __restrict__ W2, const float* __restrict__ W3,
    const float* __restrict__ Xf,
    __half* __restrict__ T0, __half* __restrict__ T1,
    __half* __restrict__ T2, __half* __restrict__ T3,
    __half* __restrict__ X16,
    int Kdim, int Ndim)
{
    if (blockIdx.z == 4) {
        // elementwise hidden convert: 4096 blocks x 2048 elems
        const int t = threadIdx.y * 32 + threadIdx.x;
        const size_t off = ((size_t)(blockIdx.y * 64 + blockIdx.x) * 2048)
                         + (size_t)t * 8;
        const float4 v0 = *(const float4*)(Xf + off);
        const float4 v1 = *(const float4*)(Xf + off + 4);
        uint2 o0, o1;
        o0.x = pack_h2(v0.x, v0.y); o0.y = pack_h2(v0.z, v0.w);
        o1.x = pack_h2(v1.x, v1.y); o1.y = pack_h2(v1.z, v1.w);
        *(uint2*)(X16 + off) = o0;
        *(uint2*)(X16 + off + 4) = o1;
        return;
    }
    __shared__ float tile[32][33];
    const float* W = (blockIdx.z == 0) ? W0 : (blockIdx.z == 1) ? W1
                   : (blockIdx.z == 2) ? W2 : W3;
    __half* T = (blockIdx.z == 0) ? T0 : (blockIdx.z == 1) ? T1
              : (blockIdx.z == 2) ? T2 : T3;
    const int tx = threadIdx.x, ty = threadIdx.y;
    const int bx = blockIdx.x, by = blockIdx.y;
    const int x = bx * 32 + tx;
    const int y = by * 32 + ty;
#pragma unroll
    for (int j = 0; j < 32; j += 8)
        tile[ty + j][tx] = W[(size_t)(y + j) * Ndim + x];
    __syncthreads();
    const int xo = by * 32 + tx;
    const int yo = bx * 32 + ty;
#pragma unroll
    for (int j = 0; j < 32; j += 8)
        T[(size_t)(yo + j) * Kdim + xo] = __float2half(tile[tx][ty + j]);
}

// ---------------------------------------------------------------------------
// Warp-MMA GEMM (fp16): unchanged (BK=64, 2 CTAs/SM, fused z instances).
// ---------------------------------------------------------------------------
#define GTM 128
#define GTN 128
#define GTK 64
#define LDT 144
#define TILE_B (128 * LDT)
#define STAGE_B (2 * TILE_B)
#define GSTAGES 3
#define GEMM_DYN (GSTAGES * STAGE_B + 256)

__device__ __forceinline__ void gemm_load_stage(
    uint32_t sbase,
    const __half* __restrict__ A, const __half* __restrict__ B,
    int m0, int n0, int k0, int K, int tid)
{
#pragma unroll
    for (int i = 0; i < 8; i++) {
        const int u = tid + i * 256;
        const int t = u >> 10;
        const int idx = u & 1023;
        const int r = idx >> 3, c = idx & 7;
        const __half* src = (t ? B + (size_t)(n0 + r) * K
                               : A + (size_t)(m0 + r) * K) + k0 + c * 8;
        CP_ASYNC16(sbase + t * TILE_B + r * LDT + c * 16, src);
    }
    CP_COMMIT();
}

__global__ __launch_bounds__(256, 2) void gemm_mma_kernel(
    const __half* __restrict__ A,
    const __half* __restrict__ B0, const __half* __restrict__ B1,
    const __half* __restrict__ B2,
    const float* __restrict__ bias0, const float* __restrict__ bias1,
    const float* __restrict__ bias2,
    float* __restrict__ Cf,
    __half* __restrict__ Ch0, __half* __restrict__ Ch1,
    __half* __restrict__ Ch2,
    float scale0, int M, int N, int K)
{
    extern __shared__ char dynsm[];
    const uint32_t sbase = (smem_to_u32(dynsm) + 127u) & ~127u;

    const int z = blockIdx.z;
    const __half* B = (z == 0) ? B0 : (z == 1) ? B1 : B2;
    const float* bias = (z == 0) ? bias0 : (z == 1) ? bias1 : bias2;
    __half* Ch = (z == 0) ? Ch0 : (z == 1) ? Ch1 : Ch2;
    const float scale = (z == 0) ? scale0 : 1.0f;

    const int tid  = threadIdx.x;
    const int wid  = tid >> 5;
    const int lane = tid & 31;
    const int wm   = wid & 1;
    const int wn   = wid >> 1;
    const int m0 = blockIdx.y * GTM;
    const int n0 = blockIdx.x * GTN;

    float acc[4][4][4];
#pragma unroll
    for (int i = 0; i < 4; i++)
#pragma unroll
        for (int j = 0; j < 4; j++)
#pragma unroll
            for (int q = 0; q < 4; q++) acc[i][j][q] = 0.f;

    const int NS = K / GTK;

    const uint32_t a_off = (uint32_t)(lane & 15) * LDT + (uint32_t)(lane >> 4) * 16;
    const uint32_t b_off = (uint32_t)((lane & 7) + ((lane >> 4) << 3)) * LDT
                         + (uint32_t)((lane >> 3) & 1) * 16;

    gemm_load_stage(sbase + 0 * STAGE_B, A, B, m0, n0, 0 * GTK, K, tid);
    gemm_load_stage(sbase + 1 * STAGE_B, A, B, m0, n0, 1 * GTK, K, tid);

    int buf = 0;
    for (int s = 0; s < NS; s++) {
        CP_WAIT1();
        __syncthreads();

        if (s + 2 < NS) {
            gemm_load_stage(sbase + ((s + 2) % GSTAGES) * STAGE_B,
                            A, B, m0, n0, (s + 2) * GTK, K, tid);
        }

        const uint32_t st = sbase + buf * STAGE_B;
        const uint32_t sA = st;
        const uint32_t sB = st + TILE_B;

#pragma unroll
        for (int ks = 0; ks < 4; ks++) {
            const uint32_t kb = ks * 32;
            uint32_t bf[4][2];
#pragma unroll
            for (int np = 0; np < 2; np++) {
                const uint32_t rowb = (uint32_t)(wn * 32 + np * 16) * LDT + kb;
                uint32_t r4[4];
                ldsm_x4(r4, sB + rowb + b_off);
                bf[np * 2][0] = r4[0]; bf[np * 2][1] = r4[1];
                bf[np * 2 + 1][0] = r4[2]; bf[np * 2 + 1][1] = r4[3];
            }
#pragma unroll
            for (int mi = 0; mi < 4; mi++) {
                const uint32_t rowb = (uint32_t)(wm * 64 + mi * 16) * LDT + kb;
                uint32_t af[4];
                ldsm_x4(af, sA + rowb + a_off);
#pragma unroll
                for (int nj = 0; nj < 4; nj++)
                    mma_f16(acc[mi][nj], af, bf[nj]);
            }
        }
        buf = (buf == GSTAGES - 1) ? 0 : buf + 1;
    }

#pragma unroll
    for (int mi = 0; mi < 4; mi++) {
        const int r0 = m0 + wm * 64 + mi * 16 + (lane >> 2);
#pragma unroll
        for (int nj = 0; nj < 4; nj++) {
            const int c = n0 + wn * 32 + nj * 8 + (lane & 3) * 2;
            const float b0 = bias[c], b1 = bias[c + 1];
            if (Cf) {
                float* p0 = Cf + (size_t)r0 * N + c;
                float* p1 = Cf + (size_t)(r0 + 8) * N + c;
                p0[0] = acc[mi][nj][0] + b0;
                p0[1] = acc[mi][nj][1] + b1;
                p1[0] = acc[mi][nj][2] + b0;
                p1[1] = acc[mi][nj][3] + b1;
            } else {
                *(uint32_t*)(Ch + (size_t)r0 * N + c) =
                    pack_h2((acc[mi][nj][0] + b0) * scale,
                            (acc[mi][nj][1] + b1) * scale);
                *(uint32_t*)(Ch + (size_t)(r0 + 8) * N + c) =
                    pack_h2((acc[mi][nj][2] + b0) * scale,
                            (acc[mi][nj][3] + b1) * scale);
            }
        }
    }
}

// ---------------------------------------------------------------------------
// FA2-style MMA flash attention (fp16). 256 threads, 8 warps, 128-row q-tile.
// Round-13 structure (best measured) + exact-math cuts:
//   - base-2 softmax (Q pre-scaled by 1/sqrt(HD)*log2e, exp2f only)
//   - diag-tile MMA skipping: warp wid's columns > wid*16+15 are fully
//     masked -> skip QK np>wid and PV ks>wid (P frags exactly zero there)
// SMEM: Q | K0 | K1 | V. 2 barriers per k-tile.
// ---------------------------------------------------------------------------
#define ATHREADS 256
#define LDAB 272
#define ATILE (128 * LDAB)            // 34816
#define OFF_Q   0
#define OFF_K0  ATILE
#define OFF_K1  (2 * ATILE)
#define OFF_V   (3 * ATILE)
#define ATT_DYN (4 * ATILE + 256)

__device__ __forceinline__ void attn_load_tile(
    uint32_t dst, const __half* __restrict__ src, size_t gbase, int tid)
{
#pragma unroll
    for (int i = 0; i < 8; i++) {
        const int u = tid + i * ATHREADS;   // 0..2047
        const int r = u >> 4;               // 0..127
        const int c = u & 15;               // 16B chunk
        CP_ASYNC16(dst + r * LDAB + c * 16,
                   (const char*)(src + gbase + (size_t)r * HDIM) + c * 16);
    }
    CP_COMMIT();
}

__global__ __launch_bounds__(ATHREADS, 1) void attn_mma_kernel(
    const __half* __restrict__ q16, const __half* __restrict__ k16,
    const __half* __restrict__ v16, __half* __restrict__ o16)
{
    extern __shared__ char dynraw[];
    char* smp = (char*)(((uintptr_t)dynraw + 127) & ~127);
    const uint32_t sbase = smem_to_u32(smp);

    const int qt  = gridDim.x - 1 - blockIdx.x;    // longest tiles first
    const int h   = blockIdx.y;
    const int b   = blockIdx.z;
    const int tid = threadIdx.x;
    const int wid = tid >> 5;                      // warp owns rows wid*16..+15
    const int lane = tid & 31;
    const int g   = lane >> 2;
    const int tig = lane & 3;

    const size_t base = (size_t)b * S_TOK * HDIM + (size_t)h * HEADDIM;
    const int q0 = qt * 128;
    const int wrow = wid * 16;

    const uint32_t a_off = (uint32_t)(lane & 15) * LDAB + (uint32_t)(lane >> 4) * 16;
    const uint32_t b_off = (uint32_t)((lane & 7) + ((lane >> 4) << 3)) * LDAB
                         + (uint32_t)((lane >> 3) & 1) * 16;
    const uint32_t v_off = (uint32_t)((lane & 7) + (((lane >> 3) & 1) << 3)) * LDAB
                         + (uint32_t)(lane >> 4) * 16;

    float m_run0 = -1e30f, m_run1 = -1e30f;
    float l_run0 = 0.f, l_run1 = 0.f;

    float o_acc[16][4];
#pragma unroll
    for (int j = 0; j < 16; j++)
#pragma unroll
        for (int q = 0; q < 4; q++) o_acc[j][q] = 0.f;

    attn_load_tile(sbase + OFF_Q, q16, base + (size_t)q0 * HDIM, tid);
    attn_load_tile(sbase + OFF_K0, k16, base, tid);

    const uint32_t qrow = (uint32_t)wrow * LDAB;

    for (int kt = 0; kt <= qt; kt++) {
        const size_t kbase = base + (size_t)kt * 128 * HDIM;
        const uint32_t kbuf = (kt & 1) ? (sbase + OFF_K1) : (sbase + OFF_K0);
        const bool diag = (kt == qt);

        CP_WAIT0();        // K[kt] (+Q on iter 0) landed for this thread
        __syncthreads();   // b0: landed for all; all warps done with prev V

        // issue V[kt] now; prefetch K[kt+1]
        attn_load_tile(sbase + OFF_V, v16, kbase, tid);
        if (kt < qt) {
            const uint32_t knext = (kt & 1) ? (sbase + OFF_K0) : (sbase + OFF_K1);
            attn_load_tile(knext, k16, kbase + (size_t)128 * HDIM, tid);
        }

        // ---- S = Q @ K^T : 16x128 stripe per warp (skip masked np on diag) ----
        float sf[16][4];
#pragma unroll
        for (int j = 0; j < 16; j++)
#pragma unroll
            for (int q = 0; q < 4; q++) sf[j][q] = 0.f;

#pragma unroll
        for (int ks = 0; ks < 8; ks++) {
            const uint32_t kb = ks * 32;
            uint32_t af[4];
            ldsm_x4(af, sbase + OFF_Q + qrow + kb + a_off);
#pragma unroll
            for (int np = 0; np < 8; np++) {
                if (!diag || np <= wid) {
                    uint32_t r4[4];
                    ldsm_x4(r4, kbuf + (uint32_t)(np * 16) * LDAB + kb + b_off);
                    mma_f16(sf[np * 2], af, r4);
                    mma_f16(sf[np * 2 + 1], af, r4 + 2);
                }
            }
        }

        // ---- causal mask (diag tile) ----
        if (diag) {
            const int r0m = wrow + g;
#pragma unroll
            for (int nj = 0; nj < 16; nj++) {
                const int c = nj * 8 + 2 * tig;
                if (c > r0m)         sf[nj][0] = -1e30f;
                if (c + 1 > r0m)     sf[nj][1] = -1e30f;
                if (c > r0m + 8)     sf[nj][2] = -1e30f;
                if (c + 1 > r0m + 8) sf[nj][3] = -1e30f;
            }
        }

        // ---- warp-local softmax (base-2) ----
        float mx0 = -1e30f, mx1 = -1e30f;
#pragma unroll
        for (int nj = 0; nj < 16; nj++) {
            mx0 = fmaxf(mx0, fmaxf(sf[nj][0], sf[nj][1]));
            mx1 = fmaxf(mx1, fmaxf(sf[nj][2], sf[nj][3]));
        }
        mx0 = fmaxf(mx0, __shfl_xor_sync(0xFFFFFFFF, mx0, 1));
        mx0 = fmaxf(mx0, __shfl_xor_sync(0xFFFFFFFF, mx0, 2));
        mx1 = fmaxf(mx1, __shfl_xor_sync(0xFFFFFFFF, mx1, 1));
        mx1 = fmaxf(mx1, __shfl_xor_sync(0xFFFFFFFF, mx1, 2));
        mx0 = fmaxf(mx0, m_run0);
        mx1 = fmaxf(mx1, m_run1);
        const float al0 = exp2f(m_run0 - mx0);
        const float al1 = exp2f(m_run1 - mx1);
        m_run0 = mx0;
        m_run1 = mx1;

        // exp2 + in-register repack: sf (C-frags) -> pf (A-frags for PV)
        uint32_t pf[8][4];
        float s0 = 0.f, s1 = 0.f;
#pragma unroll
        for (int t = 0; t < 8; t++) {
            const float e00 = exp2f(sf[2 * t][0] - mx0);
            const float e01 = exp2f(sf[2 * t][1] - mx0);
            const float e02 = exp2f(sf[2 * t][2] - mx1);
            const float e03 = exp2f(sf[2 * t][3] - mx1);
            const float e10 = exp2f(sf[2 * t + 1][0] - mx0);
            const float e11 = exp2f(sf[2 * t + 1][1] - mx0);
            const float e12 = exp2f(sf[2 * t + 1][2] - mx1);
            const float e13 = exp2f(sf[2 * t + 1][3] - mx1);
            s0 += (e00 + e01) + (e10 + e11);
            s1 += (e02 + e03) + (e12 + e13);
            pf[t][0] = pack_h2(e00, e01);
            pf[t][1] = pack_h2(e02, e03);
            pf[t][2] = pack_h2(e10, e11);
            pf[t][3] = pack_h2(e12, e13);
        }
        s0 += __shfl_xor_sync(0xFFFFFFFF, s0, 1);
        s0 += __shfl_xor_sync(0xFFFFFFFF, s0, 2);
        s1 += __shfl_xor_sync(0xFFFFFFFF, s1, 1);
        s1 += __shfl_xor_sync(0xFFFFFFFF, s1, 2);
        l_run0 = l_run0 * al0 + s0;
        l_run1 = l_run1 * al1 + s1;

#pragma unroll
        for (int nj = 0; nj < 16; nj++) {
            o_acc[nj][0] *= al0;
            o_acc[nj][1] *= al0;
            o_acc[nj][2] *= al1;
            o_acc[nj][3] *= al1;
        }

        // ---- wait V (next-K may stay in flight) ----
        if (kt < qt) { CP_WAIT1(); } else { CP_WAIT0(); }
        __syncthreads();   // b1: V landed for all

        // ---- O += P @ V (skip exactly-zero P ks-tiles on diag) ----
#pragma unroll
        for (int ks = 0; ks < 8; ks++) {
            if (!diag || ks <= wid) {
                const uint32_t vrow = (uint32_t)(ks * 16) * LDAB;
#pragma unroll
                for (int np = 0; np < 8; np++) {
                    uint32_t r4[4];
                    ldsm_x4_t(r4, sbase + OFF_V + vrow + (uint32_t)(np * 16) * 2 + v_off);
                    mma_f16(o_acc[np * 2], pf[ks], r4);
                    mma_f16(o_acc[np * 2 + 1], pf[ks], r4 + 2);
                }
            }
        }
        // next iter's b0 fences V reuse
    }

    // ---- finalize: scale by 1/l, store fp16 ----
    const float i0 = 1.f / l_run0;
    const float i1 = 1.f / l_run1;
    const size_t g0 = base + (size_t)(q0 + wrow + g) * HDIM;
    const size_t g1 = base + (size_t)(q0 + wrow + g + 8) * HDIM;
#pragma unroll
    for (int nj = 0; nj < 16; nj++) {
        const int c = nj * 8 + 2 * tig;
        *(uint32_t*)(o16 + g0 + c) = pack_h2(o_acc[nj][0] * i0, o_acc[nj][1] * i0);
        *(uint32_t*)(o16 + g1 + c) = pack_h2(o_acc[nj][2] * i1, o_acc[nj][3] * i1);
    }
}

// ---------------------------------------------------------------------------
// Launch
// ---------------------------------------------------------------------------
extern "C" void kernel_launch(void* const* d_in, const int* in_sizes, int n_in,
                              void* d_out, int out_size)
{
    const float* hidden = (const float*)d_in[0];
    // d_in[1] = attention_mask (exact causal, reproduced analytically — unused)
    const float* Wq = (const float*)d_in[2];
    const float* bq = (const float*)d_in[3];
    const float* Wk = (const float*)d_in[4];
    const float* bk = (const float*)d_in[5];
    const float* Wv = (const float*)d_in[6];
    const float* bv = (const float*)d_in[7];
    const float* Wo = (const float*)d_in[8];
    const float* bo = (const float*)d_in[9];
    float* out = (float*)d_out;

    __half *x16, *wtq, *wtk, *wtv, *wto, *q16, *k16, *v16, *o16;
    cudaGetSymbolAddress((void**)&x16, g_x16);
    cudaGetSymbolAddress((void**)&wtq, g_wtq);
    cudaGetSymbolAddress((void**)&wtk, g_wtk);
    cudaGetSymbolAddress((void**)&wtv, g_wtv);
    cudaGetSymbolAddress((void**)&wto, g_wto);
    cudaGetSymbolAddress((void**)&q16, g_q16);
    cudaGetSymbolAddress((void**)&k16, g_k16);
    cudaGetSymbolAddress((void**)&v16, g_v16);
    cudaGetSymbolAddress((void**)&o16, g_o16);

    cudaFuncSetAttribute(gemm_mma_kernel,
                         cudaFuncAttributeMaxDynamicSharedMemorySize, GEMM_DYN);
    cudaFuncSetAttribute(attn_mma_kernel,
                         cudaFuncAttributeMaxDynamicSharedMemorySize, ATT_DYN);

    // 1/sqrt(128) * log2(e): softmax runs in base-2 domain (exp2f)
    const float qscale = 0.08838834764831845f * 1.4426950408889634f;

    const dim3 qkv_grid(HDIM / GTN, MROWS / GTM, 3);   // (16, 32, 3) fused QKV
    const dim3 o_grid(HDIM / GTN, MROWS / GTM, 1);     // (16, 32, 1)
    const dim3 tgrid(HDIM / 32, HDIM / 32, 5);         // 4 weights + hidden
    const dim3 tblk(32, 8);

    convT4_kernel<<<tgrid, tblk>>>(Wq, Wk, Wv, Wo, hidden,
                                   wtq, wtk, wtv, wto, x16, HDIM, HDIM);

    // Fused Q/K/V projections (one launch, z selects instance)
    gemm_mma_kernel<<<qkv_grid, 256, GEMM_DYN>>>(
        x16, wtq, wtk, wtv, bq, bk, bv,
        nullptr, q16, k16, v16, qscale, MROWS, HDIM, HDIM);

    const dim3 attn_grid(S_TOK / 128, NHEADS, BATCH);  // (16, 16, 2)
    attn_mma_kernel<<<attn_grid, ATHREADS, ATT_DYN>>>(q16, k16, v16, o16);

    // Output projection (fp32 out)
    gemm_mma_kernel<<<o_grid, 256, GEMM_DYN>>>(
        o16, wto, wto, wto, bo, bo, bo,
        out, nullptr, nullptr, nullptr, 1.0f, MROWS, HDIM, HDIM);
}

// round 16
// speedup vs baseline: 1.0429x; 1.0429x over previous
#include <cuda_runtime.h>
#include <cuda_fp16.h>
#include <cstdint>

// Problem constants
#define S_TOK   2048
#define HDIM    2048
#define NHEADS  16
#define HEADDIM 128
#define BATCH   2
#define MROWS   (BATCH * S_TOK)   // 4096

// ---------------------------------------------------------------------------
// Scratch (alloc-free rule: __device__ globals), all single fp16
// ---------------------------------------------------------------------------
__device__ __half g_x16[(size_t)MROWS * HDIM];
__device__ __half g_wtq[(size_t)HDIM * HDIM];
__device__ __half g_wtk[(size_t)HDIM * HDIM];
__device__ __half g_wtv[(size_t)HDIM * HDIM];
__device__ __half g_wto[(size_t)HDIM * HDIM];
__device__ __half g_q16[(size_t)MROWS * HDIM];
__device__ __half g_k16[(size_t)MROWS * HDIM];
__device__ __half g_v16[(size_t)MROWS * HDIM];
__device__ __half g_o16[(size_t)MROWS * HDIM];

// ---------------------------------------------------------------------------
// MMA / ldmatrix / cp.async helpers (portable sm_80+ path; sm_103-safe)
// ---------------------------------------------------------------------------
__device__ __forceinline__ uint32_t smem_to_u32(const void* smem_ptr) {
    uint32_t addr;
    asm("{ .reg .u64 tmp; cvta.to.shared.u64 tmp, %1; cvt.u32.u64 %0, tmp; }"
        : "=r"(addr) : "l"(smem_ptr));
    return addr;
}

__device__ __forceinline__ void ldsm_x4(uint32_t* r, uint32_t addr) {
    asm volatile("ldmatrix.sync.aligned.m8n8.x4.shared.b16 {%0,%1,%2,%3}, [%4];"
                 : "=r"(r[0]), "=r"(r[1]), "=r"(r[2]), "=r"(r[3]) : "r"(addr));
}

__device__ __forceinline__ void ldsm_x4_t(uint32_t* r, uint32_t addr) {
    asm volatile("ldmatrix.sync.aligned.m8n8.x4.trans.shared.b16 {%0,%1,%2,%3}, [%4];"
                 : "=r"(r[0]), "=r"(r[1]), "=r"(r[2]), "=r"(r[3]) : "r"(addr));
}

__device__ __forceinline__ void mma_f16(float* c, const uint32_t* a,
                                        const uint32_t* b) {
    asm volatile(
        "mma.sync.aligned.m16n8k16.row.col.f32.f16.f16.f32 "
        "{%0,%1,%2,%3}, {%4,%5,%6,%7}, {%8,%9}, {%0,%1,%2,%3};"
        : "+f"(c[0]), "+f"(c[1]), "+f"(c[2]), "+f"(c[3])
        : "r"(a[0]), "r"(a[1]), "r"(a[2]), "r"(a[3]), "r"(b[0]), "r"(b[1]));
}

#define CP_ASYNC16(dst, src) \
    asm volatile("cp.async.cg.shared.global [%0], [%1], 16;" \
                 :: "r"((uint32_t)(dst)), "l"(src) : "memory")
#define CP_COMMIT() asm volatile("cp.async.commit_group;" ::: "memory")
#define CP_WAIT1()  asm volatile("cp.async.wait_group 1;" ::: "memory")
#define CP_WAIT0()  asm volatile("cp.async.wait_group 0;" ::: "memory")

__device__ __forceinline__ uint32_t pack_h2(float a, float b) {
    __half2 h = __floats2half2_rn(a, b);
    return *(uint32_t*)&h;
}

// ---------------------------------------------------------------------------
// Fused convert: z<4 -> transpose-convert weight z; z==4 -> elementwise
// convert hidden fp32 -> fp16.
// ---------------------------------------------------------------------------
__global__ __launch_bounds__(256) void convT4_kernel(
    const float* __restrict__ W0, const float* __restrict__ W1,
    const float* __restrict__ W2, const float* __restrict__ W3,
    const float* __restrict__ Xf,
    __half* __restrict__ T0, __half* __restrict__ T1,
    __half* __restrict__ T2, __half* __restrict__ T3,
    __half* __restrict__ X16,
    int Kdim, int Ndim)
{
    if (blockIdx.z == 4) {
        // elementwise hidden convert: 4096 blocks x 2048 elems
        const int t = threadIdx.y * 32 + threadIdx.x;
        const size_t off = ((size_t)(blockIdx.y * 64 + blockIdx.x) * 2048)
                         + (size_t)t * 8;
        const float4 v0 = *(const float4*)(Xf + off);
        const float4 v1 = *(const float4*)(Xf + off + 4);
        uint2 o0, o1;
        o0.x = pack_h2(v0.x, v0.y); o0.y = pack_h2(v0.z, v0.w);
        o1.x = pack_h2(v1.x, v1.y); o1.y = pack_h2(v1.z, v1.w);
        *(uint2*)(X16 + off) = o0;
        *(uint2*)(X16 + off + 4) = o1;
        return;
    }
    __shared__ float tile[32][33];
    const float* W = (blockIdx.z == 0) ? W0 : (blockIdx.z == 1) ? W1
                   : (blockIdx.z == 2) ? W2 : W3;
    __half* T = (blockIdx.z == 0) ? T0 : (blockIdx.z == 1) ? T1
              : (blockIdx.z == 2) ? T2 : T3;
    const int tx = threadIdx.x, ty = threadIdx.y;
    const int bx = blockIdx.x, by = blockIdx.y;
    const int x = bx * 32 + tx;
    const int y = by * 32 + ty;
#pragma unroll
    for (int j = 0; j < 32; j += 8)
        tile[ty + j][tx] = W[(size_t)(y + j) * Ndim + x];
    __syncthreads();
    const int xo = by * 32 + tx;
    const int yo = bx * 32 + ty;
#pragma unroll
    for (int j = 0; j < 32; j += 8)
        T[(size_t)(yo + j) * Kdim + xo] = __float2half(tile[tx][ty + j]);
}

// ---------------------------------------------------------------------------
// Warp-MMA GEMM (fp16): BK=64, 2 CTAs/SM, fused z instances (unchanged).
// ---------------------------------------------------------------------------
#define GTM 128
#define GTN 128
#define GTK 64
#define LDT 144
#define TILE_B (128 * LDT)
#define STAGE_B (2 * TILE_B)
#define GSTAGES 3
#define GEMM_DYN (GSTAGES * STAGE_B + 256)

__device__ __forceinline__ void gemm_load_stage(
    uint32_t sbase,
    const __half* __restrict__ A, const __half* __restrict__ B,
    int m0, int n0, int k0, int K, int tid)
{
#pragma unroll
    for (int i = 0; i < 8; i++) {
        const int u = tid + i * 256;
        const int t = u >> 10;
        const int idx = u & 1023;
        const int r = idx >> 3, c = idx & 7;
        const __half* src = (t ? B + (size_t)(n0 + r) * K
                               : A + (size_t)(m0 + r) * K) + k0 + c * 8;
        CP_ASYNC16(sbase + t * TILE_B + r * LDT + c * 16, src);
    }
    CP_COMMIT();
}

__global__ __launch_bounds__(256, 2) void gemm_mma_kernel(
    const __half* __restrict__ A,
    const __half* __restrict__ B0, const __half* __restrict__ B1,
    const __half* __restrict__ B2,
    const float* __restrict__ bias0, const float* __restrict__ bias1,
    const float* __restrict__ bias2,
    float* __restrict__ Cf,
    __half* __restrict__ Ch0, __half* __restrict__ Ch1,
    __half* __restrict__ Ch2,
    float scale0, int M, int N, int K)
{
    extern __shared__ char dynsm[];
    const uint32_t sbase = (smem_to_u32(dynsm) + 127u) & ~127u;

    const int z = blockIdx.z;
    const __half* B = (z == 0) ? B0 : (z == 1) ? B1 : B2;
    const float* bias = (z == 0) ? bias0 : (z == 1) ? bias1 : bias2;
    __half* Ch = (z == 0) ? Ch0 : (z == 1) ? Ch1 : Ch2;
    const float scale = (z == 0) ? scale0 : 1.0f;

    const int tid  = threadIdx.x;
    const int wid  = tid >> 5;
    const int lane = tid & 31;
    const int wm   = wid & 1;
    const int wn   = wid >> 1;
    const int m0 = blockIdx.y * GTM;
    const int n0 = blockIdx.x * GTN;

    float acc[4][4][4];
#pragma unroll
    for (int i = 0; i < 4; i++)
#pragma unroll
        for (int j = 0; j < 4; j++)
#pragma unroll
            for (int q = 0; q < 4; q++) acc[i][j][q] = 0.f;

    const int NS = K / GTK;

    const uint32_t a_off = (uint32_t)(lane & 15) * LDT + (uint32_t)(lane >> 4) * 16;
    const uint32_t b_off = (uint32_t)((lane & 7) + ((lane >> 4) << 3)) * LDT
                         + (uint32_t)((lane >> 3) & 1) * 16;

    gemm_load_stage(sbase + 0 * STAGE_B, A, B, m0, n0, 0 * GTK, K, tid);
    gemm_load_stage(sbase + 1 * STAGE_B, A, B, m0, n0, 1 * GTK, K, tid);

    int buf = 0;
    for (int s = 0; s < NS; s++) {
        CP_WAIT1();
        __syncthreads();

        if (s + 2 < NS) {
            gemm_load_stage(sbase + ((s + 2) % GSTAGES) * STAGE_B,
                            A, B, m0, n0, (s + 2) * GTK, K, tid);
        }

        const uint32_t st = sbase + buf * STAGE_B;
        const uint32_t sA = st;
        const uint32_t sB = st + TILE_B;

#pragma unroll
        for (int ks = 0; ks < 4; ks++) {
            const uint32_t kb = ks * 32;
            uint32_t bf[4][2];
#pragma unroll
            for (int np = 0; np < 2; np++) {
                const uint32_t rowb = (uint32_t)(wn * 32 + np * 16) * LDT + kb;
                uint32_t r4[4];
                ldsm_x4(r4, sB + rowb + b_off);
                bf[np * 2][0] = r4[0]; bf[np * 2][1] = r4[1];
                bf[np * 2 + 1][0] = r4[2]; bf[np * 2 + 1][1] = r4[3];
            }
#pragma unroll
            for (int mi = 0; mi < 4; mi++) {
                const uint32_t rowb = (uint32_t)(wm * 64 + mi * 16) * LDT + kb;
                uint32_t af[4];
                ldsm_x4(af, sA + rowb + a_off);
#pragma unroll
                for (int nj = 0; nj < 4; nj++)
                    mma_f16(acc[mi][nj], af, bf[nj]);
            }
        }
        buf = (buf == GSTAGES - 1) ? 0 : buf + 1;
    }

#pragma unroll
    for (int mi = 0; mi < 4; mi++) {
        const int r0 = m0 + wm * 64 + mi * 16 + (lane >> 2);
#pragma unroll
        for (int nj = 0; nj < 4; nj++) {
            const int c = n0 + wn * 32 + nj * 8 + (lane & 3) * 2;
            const float b0 = bias[c], b1 = bias[c + 1];
            if (Cf) {
                float* p0 = Cf + (size_t)r0 * N + c;
                float* p1 = Cf + (size_t)(r0 + 8) * N + c;
                p0[0] = acc[mi][nj][0] + b0;
                p0[1] = acc[mi][nj][1] + b1;
                p1[0] = acc[mi][nj][2] + b0;
                p1[1] = acc[mi][nj][3] + b1;
            } else {
                *(uint32_t*)(Ch + (size_t)r0 * N + c) =
                    pack_h2((acc[mi][nj][0] + b0) * scale,
                            (acc[mi][nj][1] + b1) * scale);
                *(uint32_t*)(Ch + (size_t)(r0 + 8) * N + c) =
                    pack_h2((acc[mi][nj][2] + b0) * scale,
                            (acc[mi][nj][3] + b1) * scale);
            }
        }
    }
}

// ---------------------------------------------------------------------------
// FA2-style MMA flash attention (fp16). 256 threads, 8 warps, 128-row q-tile.
// Round-13 structure (branch-free MMA mainloop) + base-2 softmax.
// SMEM: Q | K0 | K1 | V. 2 barriers per k-tile.
// ---------------------------------------------------------------------------
#define ATHREADS 256
#define LDAB 272
#define ATILE (128 * LDAB)            // 34816
#define OFF_Q   0
#define OFF_K0  ATILE
#define OFF_K1  (2 * ATILE)
#define OFF_V   (3 * ATILE)
#define ATT_DYN (4 * ATILE + 256)

__device__ __forceinline__ void attn_load_tile(
    uint32_t dst, const __half* __restrict__ src, size_t gbase, int tid)
{
#pragma unroll
    for (int i = 0; i < 8; i++) {
        const int u = tid + i * ATHREADS;   // 0..2047
        const int r = u >> 4;               // 0..127
        const int c = u & 15;               // 16B chunk
        CP_ASYNC16(dst + r * LDAB + c * 16,
                   (const char*)(src + gbase + (size_t)r * HDIM) + c * 16);
    }
    CP_COMMIT();
}

__global__ __launch_bounds__(ATHREADS, 1) void attn_mma_kernel(
    const __half* __restrict__ q16, const __half* __restrict__ k16,
    const __half* __restrict__ v16, __half* __restrict__ o16)
{
    extern __shared__ char dynraw[];
    char* smp = (char*)(((uintptr_t)dynraw + 127) & ~127);
    const uint32_t sbase = smem_to_u32(smp);

    const int qt  = gridDim.x - 1 - blockIdx.x;    // longest tiles first
    const int h   = blockIdx.y;
    const int b   = blockIdx.z;
    const int tid = threadIdx.x;
    const int wid = tid >> 5;                      // warp owns rows wid*16..+15
    const int lane = tid & 31;
    const int g   = lane >> 2;
    const int tig = lane & 3;

    const size_t base = (size_t)b * S_TOK * HDIM + (size_t)h * HEADDIM;
    const int q0 = qt * 128;
    const int wrow = wid * 16;

    const uint32_t a_off = (uint32_t)(lane & 15) * LDAB + (uint32_t)(lane >> 4) * 16;
    const uint32_t b_off = (uint32_t)((lane & 7) + ((lane >> 4) << 3)) * LDAB
                         + (uint32_t)((lane >> 3) & 1) * 16;
    const uint32_t v_off = (uint32_t)((lane & 7) + (((lane >> 3) & 1) << 3)) * LDAB
                         + (uint32_t)(lane >> 4) * 16;

    float m_run0 = -1e30f, m_run1 = -1e30f;
    float l_run0 = 0.f, l_run1 = 0.f;

    float o_acc[16][4];
#pragma unroll
    for (int j = 0; j < 16; j++)
#pragma unroll
        for (int q = 0; q < 4; q++) o_acc[j][q] = 0.f;

    attn_load_tile(sbase + OFF_Q, q16, base + (size_t)q0 * HDIM, tid);
    attn_load_tile(sbase + OFF_K0, k16, base, tid);

    const uint32_t qrow = (uint32_t)wrow * LDAB;

    for (int kt = 0; kt <= qt; kt++) {
        const size_t kbase = base + (size_t)kt * 128 * HDIM;
        const uint32_t kbuf = (kt & 1) ? (sbase + OFF_K1) : (sbase + OFF_K0);

        CP_WAIT0();        // K[kt] (+Q on iter 0) landed for this thread
        __syncthreads();   // b0: landed for all; all warps done with prev V

        // issue V[kt] now; prefetch K[kt+1]
        attn_load_tile(sbase + OFF_V, v16, kbase, tid);
        if (kt < qt) {
            const uint32_t knext = (kt & 1) ? (sbase + OFF_K0) : (sbase + OFF_K1);
            attn_load_tile(knext, k16, kbase + (size_t)128 * HDIM, tid);
        }

        // ---- S = Q @ K^T : full 16x128 stripe per warp (branch-free) ----
        float sf[16][4];
#pragma unroll
        for (int j = 0; j < 16; j++)
#pragma unroll
            for (int q = 0; q < 4; q++) sf[j][q] = 0.f;

#pragma unroll
        for (int ks = 0; ks < 8; ks++) {
            const uint32_t kb = ks * 32;
            uint32_t af[4];
            ldsm_x4(af, sbase + OFF_Q + qrow + kb + a_off);
#pragma unroll
            for (int np = 0; np < 8; np++) {
                uint32_t r4[4];
                ldsm_x4(r4, kbuf + (uint32_t)(np * 16) * LDAB + kb + b_off);
                mma_f16(sf[np * 2], af, r4);
                mma_f16(sf[np * 2 + 1], af, r4 + 2);
            }
        }

        // ---- causal mask (diag tile) ----
        if (kt == qt) {
            const int r0m = wrow + g;
#pragma unroll
            for (int nj = 0; nj < 16; nj++) {
                const int c = nj * 8 + 2 * tig;
                if (c > r0m)         sf[nj][0] = -1e30f;
                if (c + 1 > r0m)     sf[nj][1] = -1e30f;
                if (c > r0m + 8)     sf[nj][2] = -1e30f;
                if (c + 1 > r0m + 8) sf[nj][3] = -1e30f;
            }
        }

        // ---- warp-local softmax (base-2; Q pre-scaled by log2e/sqrt(HD)) ----
        float mx0 = -1e30f, mx1 = -1e30f;
#pragma unroll
        for (int nj = 0; nj < 16; nj++) {
            mx0 = fmaxf(mx0, fmaxf(sf[nj][0], sf[nj][1]));
            mx1 = fmaxf(mx1, fmaxf(sf[nj][2], sf[nj][3]));
        }
        mx0 = fmaxf(mx0, __shfl_xor_sync(0xFFFFFFFF, mx0, 1));
        mx0 = fmaxf(mx0, __shfl_xor_sync(0xFFFFFFFF, mx0, 2));
        mx1 = fmaxf(mx1, __shfl_xor_sync(0xFFFFFFFF, mx1, 1));
        mx1 = fmaxf(mx1, __shfl_xor_sync(0xFFFFFFFF, mx1, 2));
        mx0 = fmaxf(mx0, m_run0);
        mx1 = fmaxf(mx1, m_run1);
        const float al0 = exp2f(m_run0 - mx0);
        const float al1 = exp2f(m_run1 - mx1);
        m_run0 = mx0;
        m_run1 = mx1;

        // exp2 + in-register repack: sf (C-frags) -> pf (A-frags for PV)
        uint32_t pf[8][4];
        float s0 = 0.f, s1 = 0.f;
#pragma unroll
        for (int t = 0; t < 8; t++) {
            const float e00 = exp2f(sf[2 * t][0] - mx0);
            const float e01 = exp2f(sf[2 * t][1] - mx0);
            const float e02 = exp2f(sf[2 * t][2] - mx1);
            const float e03 = exp2f(sf[2 * t][3] - mx1);
            const float e10 = exp2f(sf[2 * t + 1][0] - mx0);
            const float e11 = exp2f(sf[2 * t + 1][1] - mx0);
            const float e12 = exp2f(sf[2 * t + 1][2] - mx1);
            const float e13 = exp2f(sf[2 * t + 1][3] - mx1);
            s0 += (e00 + e01) + (e10 + e11);
            s1 += (e02 + e03) + (e12 + e13);
            pf[t][0] = pack_h2(e00, e01);
            pf[t][1] = pack_h2(e02, e03);
            pf[t][2] = pack_h2(e10, e11);
            pf[t][3] = pack_h2(e12, e13);
        }
        s0 += __shfl_xor_sync(0xFFFFFFFF, s0, 1);
        s0 += __shfl_xor_sync(0xFFFFFFFF, s0, 2);
        s1 += __shfl_xor_sync(0xFFFFFFFF, s1, 1);
        s1 += __shfl_xor_sync(0xFFFFFFFF, s1, 2);
        l_run0 = l_run0 * al0 + s0;
        l_run1 = l_run1 * al1 + s1;

        // rescale o_acc
#pragma unroll
        for (int nj = 0; nj < 16; nj++) {
            o_acc[nj][0] *= al0;
            o_acc[nj][1] *= al0;
            o_acc[nj][2] *= al1;
            o_acc[nj][3] *= al1;
        }

        // ---- wait V (next-K may stay in flight) ----
        if (kt < qt) { CP_WAIT1(); } else { CP_WAIT0(); }
        __syncthreads();   // b1: V landed for all

        // ---- O += P @ V (P in registers, V via trans ldsm; branch-free) ----
#pragma unroll
        for (int ks = 0; ks < 8; ks++) {
            const uint32_t vrow = (uint32_t)(ks * 16) * LDAB;
#pragma unroll
            for (int np = 0; np < 8; np++) {
                uint32_t r4[4];
                ldsm_x4_t(r4, sbase + OFF_V + vrow + (uint32_t)(np * 16) * 2 + v_off);
                mma_f16(o_acc[np * 2], pf[ks], r4);
                mma_f16(o_acc[np * 2 + 1], pf[ks], r4 + 2);
            }
        }
        // next iter's b0 fences V reuse
    }

    // ---- finalize: scale by 1/l, store fp16 ----
    const float i0 = 1.f / l_run0;
    const float i1 = 1.f / l_run1;
    const size_t g0 = base + (size_t)(q0 + wrow + g) * HDIM;
    const size_t g1 = base + (size_t)(q0 + wrow + g + 8) * HDIM;
#pragma unroll
    for (int nj = 0; nj < 16; nj++) {
        const int c = nj * 8 + 2 * tig;
        *(uint32_t*)(o16 + g0 + c) = pack_h2(o_acc[nj][0] * i0, o_acc[nj][1] * i0);
        *(uint32_t*)(o16 + g1 + c) = pack_h2(o_acc[nj][2] * i1, o_acc[nj][3] * i1);
    }
}

// ---------------------------------------------------------------------------
// Launch
// ---------------------------------------------------------------------------
extern "C" void kernel_launch(void* const* d_in, const int* in_sizes, int n_in,
                              void* d_out, int out_size)
{
    const float* hidden = (const float*)d_in[0];
    // d_in[1] = attention_mask (exact causal, reproduced analytically — unused)
    const float* Wq = (const float*)d_in[2];
    const float* bq = (const float*)d_in[3];
    const float* Wk = (const float*)d_in[4];
    const float* bk = (const float*)d_in[5];
    const float* Wv = (const float*)d_in[6];
    const float* bv = (const float*)d_in[7];
    const float* Wo = (const float*)d_in[8];
    const float* bo = (const float*)d_in[9];
    float* out = (float*)d_out;

    __half *x16, *wtq, *wtk, *wtv, *wto, *q16, *k16, *v16, *o16;
    cudaGetSymbolAddress((void**)&x16, g_x16);
    cudaGetSymbolAddress((void**)&wtq, g_wtq);
    cudaGetSymbolAddress((void**)&wtk, g_wtk);
    cudaGetSymbolAddress((void**)&wtv, g_wtv);
    cudaGetSymbolAddress((void**)&wto, g_wto);
    cudaGetSymbolAddress((void**)&q16, g_q16);
    cudaGetSymbolAddress((void**)&k16, g_k16);
    cudaGetSymbolAddress((void**)&v16, g_v16);
    cudaGetSymbolAddress((void**)&o16, g_o16);

    cudaFuncSetAttribute(gemm_mma_kernel,
                         cudaFuncAttributeMaxDynamicSharedMemorySize, GEMM_DYN);
    cudaFuncSetAttribute(attn_mma_kernel,
                         cudaFuncAttributeMaxDynamicSharedMemorySize, ATT_DYN);

    // 1/sqrt(128) * log2(e): softmax runs in base-2 domain (exp2f)
    const float qscale = 0.08838834764831845f * 1.4426950408889634f;

    const dim3 qkv_grid(HDIM / GTN, MROWS / GTM, 3);   // (16, 32, 3) fused QKV
    const dim3 o_grid(HDIM / GTN, MROWS / GTM, 1);     // (16, 32, 1)
    const dim3 tgrid(HDIM / 32, HDIM / 32, 5);         // 4 weights + hidden
    const dim3 tblk(32, 8);

    convT4_kernel<<<tgrid, tblk>>>(Wq, Wk, Wv, Wo, hidden,
                                   wtq, wtk, wtv, wto, x16, HDIM, HDIM);

    // Fused Q/K/V projections (one launch, z selects instance)
    gemm_mma_kernel<<<qkv_grid, 256, GEMM_DYN>>>(
        x16, wtq, wtk, wtv, bq, bk, bv,
        nullptr, q16, k16, v16, qscale, MROWS, HDIM, HDIM);

    const dim3 attn_grid(S_TOK / 128, NHEADS, BATCH);  // (16, 16, 2)
    attn_mma_kernel<<<attn_grid, ATHREADS, ATT_DYN>>>(q16, k16, v16, o16);

    // Output projection (fp32 out)
    gemm_mma_kernel<<<o_grid, 256, GEMM_DYN>>>(
        o16, wto, wto, wto, bo, bo, bo,
        out, nullptr, nullptr, nullptr, 1.0f, MROWS, HDIM, HDIM);
}